// round 1
// baseline (speedup 1.0000x reference)
#include <cuda_runtime.h>
#include <math.h>

// Problem constants
#define NN     256
#define NCOIL  8
#define KTOT   17408
#define NVEC   512
#define KT     32          // k-values per block

// Scratch: Xc[a][b][coil-pair] as float4 (c0.re, c0.im, c1.re, c1.im)
// Layout index: (a*NN + b)*4 + pair   -> 4 MB, L2-resident.
__device__ float4 g_Xc4[NN * NN * (NCOIL / 2)];

// ---------------------------------------------------------------------------
// Prep: Xc[c,a,b] = C[c,a,b] * x[a,b]   (complex multiply), interleaved by coil pair
// ---------------------------------------------------------------------------
__global__ void prep_kernel(const float* __restrict__ input_r,
                            const float* __restrict__ C_r) {
    int ab = blockIdx.x * blockDim.x + threadIdx.x;   // ab = a*256 + b
    if (ab >= NN * NN) return;
    float xr = input_r[ab * 2 + 0];
    float xi = input_r[ab * 2 + 1];
#pragma unroll
    for (int p = 0; p < NCOIL / 2; ++p) {
        int c0 = 2 * p;
        float C0r = C_r[((c0 + 0) * NN * NN + ab) * 2 + 0];
        float C0i = C_r[((c0 + 0) * NN * NN + ab) * 2 + 1];
        float C1r = C_r[((c0 + 1) * NN * NN + ab) * 2 + 0];
        float C1i = C_r[((c0 + 1) * NN * NN + ab) * 2 + 1];
        g_Xc4[ab * (NCOIL / 2) + p] =
            make_float4(C0r * xr - C0i * xi, C0r * xi + C0i * xr,
                        C1r * xr - C1i * xi, C1r * xi + C1i * xr);
    }
}

// ---------------------------------------------------------------------------
// Main kernel.
//   Block: 256 threads = 8 warps, covers KT=32 k-values and all 8 coils.
//   Warp w: coil pair (w & 3), b-half (w >> 2).  Lane = k within tile.
//   Inner loop (hot): per b: 1 uniform LDG.128 (Xc pair) + 1 LDS.64 (E2)
//                     + 8 FFMA  -> 64 cmacs / 4 cyc / SM-warp  -> FFMA-bound.
//   E2 tile cached in dynamic smem (64 KB); E1 via per-lane rotation recurrence.
//   b-halves combined through smem at the end; scaled by w[k % 512].
// ---------------------------------------------------------------------------
extern __shared__ float smem_raw[];

__global__ void __launch_bounds__(256, 2)
main_kernel(const float* __restrict__ angle,
            const float* __restrict__ w,
            float* __restrict__ out) {
    float2 (*e2s)[KT] = (float2(*)[KT])smem_raw;   // [256][KT] = 64 KB

    const int tid  = threadIdx.x;
    const int lane = tid & 31;
    const int wid  = tid >> 5;
    const int kblk = blockIdx.x * KT;

    // ---- fill E2 tile: e2s[b][kl] = exp(i * t_k * (b-128)) ----
    {
        const int kl = lane;                  // KT == 32
        const float t = angle[2 * (kblk + kl) + 1];
        for (int b = wid; b < NN; b += 8) {
            float ph = t * (float)(b - NN / 2);
            float sv, cv;
            sincosf(ph, &sv, &cv);
            e2s[b][kl] = make_float2(cv, sv);
        }
    }
    __syncthreads();

    const int cp   = wid & 3;        // coil pair 0..3
    const int half = wid >> 2;       // b-half 0/1
    const int b0   = half * (NN / 2);
    const int k    = kblk + lane;

    const float s = angle[2 * k + 0];
    // E1 rotation state: e1 = exp(i*s*(a-128)) starting at a=0, step exp(i*s)
    float e1r, e1i, str_, sti;
    sincosf(s * (float)(-(NN / 2)), &e1i, &e1r);
    sincosf(s, &sti, &str_);

    float y0r = 0.f, y0i = 0.f, y1r = 0.f, y1i = 0.f;

    for (int a = 0; a < NN; ++a) {
        float t0r = 0.f, t0i = 0.f, t1r = 0.f, t1i = 0.f;
        const float4* p = g_Xc4 + (a * NN + b0) * (NCOIL / 2) + cp;
#pragma unroll 8
        for (int b = 0; b < NN / 2; ++b) {
            float4 X = __ldg(p + b * (NCOIL / 2));   // uniform across warp
            float2 e = e2s[b0 + b][lane];
            t0r = fmaf(X.x, e.x, t0r);  t0r = fmaf(-X.y, e.y, t0r);
            t0i = fmaf(X.x, e.y, t0i);  t0i = fmaf( X.y, e.x, t0i);
            t1r = fmaf(X.z, e.x, t1r);  t1r = fmaf(-X.w, e.y, t1r);
            t1i = fmaf(X.z, e.y, t1i);  t1i = fmaf( X.w, e.x, t1i);
        }
        // y += e1 * t  (complex)
        y0r = fmaf(e1r, t0r, y0r);  y0r = fmaf(-e1i, t0i, y0r);
        y0i = fmaf(e1r, t0i, y0i);  y0i = fmaf( e1i, t0r, y0i);
        y1r = fmaf(e1r, t1r, y1r);  y1r = fmaf(-e1i, t1i, y1r);
        y1i = fmaf(e1r, t1i, y1i);  y1i = fmaf( e1i, t1r, y1i);
        // rotate e1 by exp(i*s)
        float nr = e1r * str_ - e1i * sti;
        e1i = fmaf(e1r, sti, e1i * str_);
        e1r = nr;
    }

    // ---- combine the two b-halves, scale by w, write out ----
    __syncthreads();                       // everyone done reading e2s
    float4* buf = (float4*)smem_raw;       // reuse smem: [4][32]
    if (half == 1) {
        buf[cp * 32 + lane] = make_float4(y0r, y0i, y1r, y1i);
    }
    __syncthreads();
    if (half == 0) {
        float4 o = buf[cp * 32 + lane];
        float wk = w[k & (NVEC - 1)];
        int c0 = cp * 2;
        float* o0 = out + ((size_t)(c0 + 0) * KTOT + k) * 2;
        float* o1 = out + ((size_t)(c0 + 1) * KTOT + k) * 2;
        o0[0] = (y0r + o.x) * wk;
        o0[1] = (y0i + o.y) * wk;
        o1[0] = (y1r + o.z) * wk;
        o1[1] = (y1i + o.w) * wk;
    }
}

// ---------------------------------------------------------------------------
extern "C" void kernel_launch(void* const* d_in, const int* in_sizes, int n_in,
                              void* d_out, int out_size) {
    const float* input_r = (const float*)d_in[0];   // (256,256,2)
    const float* C_r     = (const float*)d_in[1];   // (8,256,256,2)
    const float* w       = (const float*)d_in[2];   // (512,)
    const float* angle   = (const float*)d_in[3];   // (17408,2)
    float* out = (float*)d_out;                     // (8,17408,2)

    prep_kernel<<<(NN * NN + 255) / 256, 256>>>(input_r, C_r);

    static_assert(KTOT % KT == 0, "tile");
    cudaFuncSetAttribute(main_kernel,
                         cudaFuncAttributeMaxDynamicSharedMemorySize, 65536);
    main_kernel<<<KTOT / KT, 256, 65536>>>(angle, w, out);
}

// round 3
// speedup vs baseline: 6.6883x; 6.6883x over previous
#include <cuda_runtime.h>
#include <cstdint>
#include <math.h>

#define NN     256
#define NCOIL  8
#define KTOT   17408
#define NVEC   512
#define KT_CTA 64                 // k rows per CTA
#define NCTA   (KTOT / KT_CTA)    // 272

// E2 smem plane: 64 k-rows x 260 floats (stride-pad 4)
#define E2STR   260
#define E2PLANE (64 * E2STR * 4)          // 66560 B
// Xc stage: 32 cols x 132 floats (pad 4)
#define COLSTR  132
#define XPLANE  (32 * COLSTR * 4)         // 16896 B
#define XBUF    (2 * XPLANE)              // 33792 B (r + i planes)
#define XBASE   (2 * E2PLANE)             // 133120
#define SMEM_BYTES (XBASE + 2 * XBUF)     // 200704

// Global scratch: Xc split re/im, row-major [(c*256+a)][b], tf32-rounded
__device__ float gXr[(size_t)NCOIL * NN * NN];
__device__ float gXi[(size_t)NCOIL * NN * NN];

// ------------------------- helpers -------------------------
__device__ __forceinline__ uint32_t smem_u32(const void* p) {
    uint32_t a;
    asm("{ .reg .u64 t; cvta.to.shared.u64 t, %1; cvt.u32.u64 %0, t; }"
        : "=r"(a) : "l"(p));
    return a;
}
__device__ __forceinline__ float tf32r(float x) {
    uint32_t u;
    asm("cvt.rna.tf32.f32 %0, %1;" : "=r"(u) : "f"(x));
    return __uint_as_float(u);
}
__device__ __forceinline__ void cp16(uint32_t dst, const float* src) {
    asm volatile("cp.async.cg.shared.global [%0], [%1], 16;"
                 :: "r"(dst), "l"(src) : "memory");
}
#define CP_COMMIT() asm volatile("cp.async.commit_group;" ::: "memory")
#define CP_WAIT(n)  asm volatile("cp.async.wait_group %0;" :: "n"(n) : "memory")

__device__ __forceinline__ uint32_t lds1(uint32_t a) {
    uint32_t v;
    asm("ld.shared.b32 %0, [%1];" : "=r"(v) : "r"(a));
    return v;
}
__device__ __forceinline__ void sts1(uint32_t a, float v) {
    asm volatile("st.shared.b32 [%0], %1;" :: "r"(a), "f"(v));
}
// tf32 m16n8k8 mma, fp32 accumulate (sm_80+ PTX, works under compute_103)
__device__ __forceinline__ void mma8(float* d, const uint32_t* A,
                                     uint32_t b0, uint32_t b1) {
    asm volatile(
        "mma.sync.aligned.m16n8k8.row.col.f32.tf32.tf32.f32 "
        "{%0,%1,%2,%3}, {%4,%5,%6,%7}, {%8,%9}, {%0,%1,%2,%3};"
        : "+f"(d[0]), "+f"(d[1]), "+f"(d[2]), "+f"(d[3])
        : "r"(A[0]), "r"(A[1]), "r"(A[2]), "r"(A[3]), "r"(b0), "r"(b1));
}

// ------------------------- prep -------------------------
__global__ void prep_X(const float* __restrict__ input_r,
                       const float* __restrict__ C_r) {
    int idx = blockIdx.x * blockDim.x + threadIdx.x;   // (c*256+a)*256 + b
    if (idx >= NCOIL * NN * NN) return;
    int n = idx >> 8;            // c*256+a
    int b = idx & 255;
    int a = n & 255;
    float xr = input_r[(a * NN + b) * 2 + 0];
    float xi = input_r[(a * NN + b) * 2 + 1];
    float cr = C_r[(size_t)idx * 2 + 0];
    float ci = C_r[(size_t)idx * 2 + 1];
    gXr[idx] = tf32r(cr * xr - ci * xi);
    gXi[idx] = tf32r(cr * xi + ci * xr);
}

// ------------------------- main -------------------------
extern __shared__ char dyn_smem[];

__global__ void __launch_bounds__(256, 1)
main_kernel(const float* __restrict__ angle, const float* __restrict__ w,
            float* __restrict__ out) {
    __shared__ float2 sred[KT_CTA];

    const uint32_t sb  = smem_u32(dyn_smem);
    const uint32_t E2R = sb;
    const uint32_t E2I = sb + E2PLANE;
    const uint32_t XST = sb + XBASE;

    const int tid  = threadIdx.x;
    const int lane = tid & 31;
    const int warp = tid >> 5;
    const int kw   = warp & 3;        // k-subtile (16 rows each)
    const int nw   = warp >> 2;       // n-half (16 cols each)
    const int r    = lane >> 2;
    const int q    = lane & 3;
    const int kblk = blockIdx.x * KT_CTA;

    // ---- synthesize E2 tile in smem (tf32-rounded) ----
    {
        int kl = tid >> 2;            // 0..63
        int b0 = (tid & 3) * 64;      // segment start
        float t = angle[2 * (kblk + kl) + 1];
        float er, ei, sc, ss;
        sincosf(t * (float)(b0 - 128), &ei, &er);
        sincosf(t, &ss, &sc);
        uint32_t off = (uint32_t)(kl * E2STR + b0) * 4;
        for (int i = 0; i < 64; ++i) {
            sts1(E2R + off, tf32r(er));
            sts1(E2I + off, tf32r(ei));
            off += 4;
            float nr = er * sc - ei * ss;
            ei = fmaf(er, ss, ei * sc);
            er = nr;
        }
    }

    // ---- per-thread E1 constants ----
    const int k0g = kblk + kw * 16 + r;
    const int k1g = k0g + 8;
    const float s0 = angle[2 * k0g];
    const float s1 = angle[2 * k1g];
    float sttr[2], stti[2], advr[2], advi[2], facr[2][4], faci[2][4];
    {
        const float ss[2] = {s0, s1};
#pragma unroll
        for (int m = 0; m < 2; ++m) {
            sincosf(-128.0f * ss[m], &stti[m], &sttr[m]);
            sincosf(32.0f * ss[m], &advi[m], &advr[m]);
            const int co0 = nw * 16 + 2 * q;
#pragma unroll
            for (int idx = 0; idx < 4; ++idx) {
                int co = co0 + (idx >> 1) * 8 + (idx & 1);   // idx = nt*2+j
                sincosf(ss[m] * (float)co, &faci[m][idx], &facr[m][idx]);
            }
        }
    }
    const float wk0 = w[k0g & (NVEC - 1)];
    const float wk1 = w[k1g & (NVEC - 1)];

    __syncthreads();   // E2 ready

    // ---- stage loader: stage st -> (c, ach, half), buffer st&1 ----
    const int lcol = tid >> 3;          // 0..31
    const int lbs  = (tid & 7) * 16;    // b-segment within 128
    auto issue_load = [&](int st) {
        int c    = st >> 4;
        int ach  = (st >> 1) & 7;
        int half = st & 1;
        uint32_t dst = XST + (uint32_t)(st & 1) * XBUF
                     + (uint32_t)(lcol * COLSTR + lbs) * 4;
        size_t src = ((size_t)(c * 256 + ach * 32 + lcol) << 8) + half * 128 + lbs;
        const float* pr = gXr + src;
        const float* pi = gXi + src;
#pragma unroll
        for (int i = 0; i < 4; ++i) {
            cp16(dst + i * 16,          pr + i * 4);
            cp16(dst + XPLANE + i * 16, pi + i * 4);
        }
        CP_COMMIT();
    };

    float y0r = 0.f, y0i = 0.f, y1r = 0.f, y1i = 0.f;
    float str_[2] = {sttr[0], sttr[1]}, sti_[2] = {stti[0], stti[1]};

    issue_load(0);

#pragma unroll 1
    for (int c = 0; c < NCOIL; ++c) {
#pragma unroll 1
        for (int ach = 0; ach < 8; ++ach) {
            float acc[2][4][4];
#pragma unroll
            for (int nt = 0; nt < 2; ++nt)
#pragma unroll
                for (int p = 0; p < 4; ++p)
#pragma unroll
                    for (int e = 0; e < 4; ++e) acc[nt][p][e] = 0.f;

#pragma unroll 1
            for (int half = 0; half < 2; ++half) {
                const int cur = (c * 8 + ach) * 2 + half;
                if (cur + 1 < 128) { issue_load(cur + 1); CP_WAIT(1); }
                else               { CP_WAIT(0); }
                __syncthreads();

                const uint32_t xb = XST + (uint32_t)(cur & 1) * XBUF;
                // A base addrs (E2), b-global = half*128
                uint32_t aR = E2R + (uint32_t)((kw * 16 + r) * E2STR + half * 128 + q) * 4;
                uint32_t aI = aR + (E2I - E2R);
                uint32_t bA0 = xb + (uint32_t)((nw * 16 + 0 * 8 + r) * COLSTR + q) * 4;
                uint32_t bA1 = xb + (uint32_t)((nw * 16 + 1 * 8 + r) * COLSTR + q) * 4;

#pragma unroll 4
                for (int bs = 0; bs < 16; ++bs) {
                    uint32_t Ar[4], Ai[4];
                    Ar[0] = lds1(aR);            Ar[1] = lds1(aR + 8320);
                    Ar[2] = lds1(aR + 16);       Ar[3] = lds1(aR + 8336);
                    Ai[0] = lds1(aI);            Ai[1] = lds1(aI + 8320);
                    Ai[2] = lds1(aI + 16);       Ai[3] = lds1(aI + 8336);
                    uint32_t b0r = lds1(bA0),          b0r4 = lds1(bA0 + 16);
                    uint32_t b0i = lds1(bA0 + XPLANE), b0i4 = lds1(bA0 + XPLANE + 16);
                    uint32_t b1r = lds1(bA1),          b1r4 = lds1(bA1 + 16);
                    uint32_t b1i = lds1(bA1 + XPLANE), b1i4 = lds1(bA1 + XPLANE + 16);

                    mma8(acc[0][0], Ar, b0r, b0r4);
                    mma8(acc[0][1], Ar, b0i, b0i4);
                    mma8(acc[0][2], Ai, b0r, b0r4);
                    mma8(acc[0][3], Ai, b0i, b0i4);
                    mma8(acc[1][0], Ar, b1r, b1r4);
                    mma8(acc[1][1], Ar, b1i, b1i4);
                    mma8(acc[1][2], Ai, b1r, b1r4);
                    mma8(acc[1][3], Ai, b1i, b1i4);

                    aR += 32; aI += 32; bA0 += 32; bA1 += 32;
                }
                __syncthreads();
            }

            // ---- epilogue: y += e1 * T for this a-chunk ----
#pragma unroll
            for (int nt = 0; nt < 2; ++nt)
#pragma unroll
                for (int m = 0; m < 2; ++m)
#pragma unroll
                    for (int j = 0; j < 2; ++j) {
                        int e = m * 2 + j;
                        float Tr = acc[nt][0][e] - acc[nt][3][e];
                        float Ti = acc[nt][1][e] + acc[nt][2][e];
                        int idx = nt * 2 + j;
                        float er = str_[m] * facr[m][idx] - sti_[m] * faci[m][idx];
                        float ei = str_[m] * faci[m][idx] + sti_[m] * facr[m][idx];
                        if (m == 0) {
                            y0r = fmaf(er, Tr, y0r); y0r = fmaf(-ei, Ti, y0r);
                            y0i = fmaf(er, Ti, y0i); y0i = fmaf(ei, Tr, y0i);
                        } else {
                            y1r = fmaf(er, Tr, y1r); y1r = fmaf(-ei, Ti, y1r);
                            y1i = fmaf(er, Ti, y1i); y1i = fmaf(ei, Tr, y1i);
                        }
                    }
            // advance rotation state by 32 a
#pragma unroll
            for (int m = 0; m < 2; ++m) {
                float nr = str_[m] * advr[m] - sti_[m] * advi[m];
                sti_[m] = fmaf(str_[m], advi[m], sti_[m] * advr[m]);
                str_[m] = nr;
            }
        }

        // ---- reduce across lanes/warps and write coil c ----
        y0r += __shfl_xor_sync(0xffffffff, y0r, 1); y0r += __shfl_xor_sync(0xffffffff, y0r, 2);
        y0i += __shfl_xor_sync(0xffffffff, y0i, 1); y0i += __shfl_xor_sync(0xffffffff, y0i, 2);
        y1r += __shfl_xor_sync(0xffffffff, y1r, 1); y1r += __shfl_xor_sync(0xffffffff, y1r, 2);
        y1i += __shfl_xor_sync(0xffffffff, y1i, 1); y1i += __shfl_xor_sync(0xffffffff, y1i, 2);

        if (nw == 1 && q == 0) {
            sred[kw * 16 + r]     = make_float2(y0r, y0i);
            sred[kw * 16 + 8 + r] = make_float2(y1r, y1i);
        }
        __syncthreads();
        if (nw == 0 && q == 0) {
            float2 p0 = sred[kw * 16 + r];
            float2 p1 = sred[kw * 16 + 8 + r];
            size_t o0 = ((size_t)c * KTOT + k0g) * 2;
            size_t o1 = ((size_t)c * KTOT + k1g) * 2;
            out[o0 + 0] = (y0r + p0.x) * wk0;
            out[o0 + 1] = (y0i + p0.y) * wk0;
            out[o1 + 0] = (y1r + p1.x) * wk1;
            out[o1 + 1] = (y1i + p1.y) * wk1;
        }
        __syncthreads();

        // reset for next coil
        y0r = y0i = y1r = y1i = 0.f;
#pragma unroll
        for (int m = 0; m < 2; ++m) { str_[m] = sttr[m]; sti_[m] = stti[m]; }
    }
}

// ------------------------- launch -------------------------
extern "C" void kernel_launch(void* const* d_in, const int* in_sizes, int n_in,
                              void* d_out, int out_size) {
    const float* input_r = (const float*)d_in[0];
    const float* C_r     = (const float*)d_in[1];
    const float* w       = (const float*)d_in[2];
    const float* angle   = (const float*)d_in[3];
    float* out = (float*)d_out;

    prep_X<<<(NCOIL * NN * NN + 255) / 256, 256>>>(input_r, C_r);

    cudaFuncSetAttribute(main_kernel,
                         cudaFuncAttributeMaxDynamicSharedMemorySize, SMEM_BYTES);
    main_kernel<<<NCTA, 256, SMEM_BYTES>>>(angle, w, out);
}

// round 4
// speedup vs baseline: 7.2042x; 1.0771x over previous
#include <cuda_runtime.h>
#include <cstdint>
#include <math.h>

#define NN     256
#define NCOIL  8
#define KTOT   17408
#define NVEC   512
#define KT_CTA 64                 // k rows per CTA
#define NCTA   (KTOT / KT_CTA)    // 272

// Xc stage: 32 a-cols x 68 floats (64 b + pad 4), r+i planes, 4 buffers
#define COLSTR  68
#define PLANE   (32 * COLSTR * 4)     // 8704 B
#define XBUF    (2 * PLANE)           // 17408 B
#define NBUF    4
#define SMEM_BYTES (NBUF * XBUF)      // 69632 B
#define NSTAGE  256                   // 8 coils * 8 ach * 4 qtr

// Global scratch: Xc split re/im, row-major [(c*256+a)][b], tf32-rounded
__device__ float gXr[(size_t)NCOIL * NN * NN];
__device__ float gXi[(size_t)NCOIL * NN * NN];

// ------------------------- helpers -------------------------
__device__ __forceinline__ uint32_t smem_u32(const void* p) {
    uint32_t a;
    asm("{ .reg .u64 t; cvta.to.shared.u64 t, %1; cvt.u32.u64 %0, t; }"
        : "=r"(a) : "l"(p));
    return a;
}
__device__ __forceinline__ float tf32r(float x) {
    uint32_t u;
    asm("cvt.rna.tf32.f32 %0, %1;" : "=r"(u) : "f"(x));
    return __uint_as_float(u);
}
__device__ __forceinline__ uint32_t tf32u(float x) {
    uint32_t u;
    asm("cvt.rna.tf32.f32 %0, %1;" : "=r"(u) : "f"(x));
    return u;
}
__device__ __forceinline__ void cp16(uint32_t dst, const float* src) {
    asm volatile("cp.async.cg.shared.global [%0], [%1], 16;"
                 :: "r"(dst), "l"(src) : "memory");
}
#define CP_COMMIT() asm volatile("cp.async.commit_group;" ::: "memory")
#define CP_WAIT(n)  asm volatile("cp.async.wait_group %0;" :: "n"(n) : "memory")

__device__ __forceinline__ uint32_t lds1(uint32_t a) {
    uint32_t v;
    asm("ld.shared.b32 %0, [%1];" : "=r"(v) : "r"(a));
    return v;
}
// tf32 m16n8k8 mma, fp32 accumulate
__device__ __forceinline__ void mma8(float* d, const uint32_t* A,
                                     uint32_t b0, uint32_t b1) {
    asm volatile(
        "mma.sync.aligned.m16n8k8.row.col.f32.tf32.tf32.f32 "
        "{%0,%1,%2,%3}, {%4,%5,%6,%7}, {%8,%9}, {%0,%1,%2,%3};"
        : "+f"(d[0]), "+f"(d[1]), "+f"(d[2]), "+f"(d[3])
        : "r"(A[0]), "r"(A[1]), "r"(A[2]), "r"(A[3]), "r"(b0), "r"(b1));
}

// ------------------------- prep -------------------------
__global__ void prep_X(const float* __restrict__ input_r,
                       const float* __restrict__ C_r) {
    int idx = blockIdx.x * blockDim.x + threadIdx.x;   // (c*256+a)*256 + b
    if (idx >= NCOIL * NN * NN) return;
    int n = idx >> 8;
    int b = idx & 255;
    int a = n & 255;
    float xr = input_r[(a * NN + b) * 2 + 0];
    float xi = input_r[(a * NN + b) * 2 + 1];
    float cr = C_r[(size_t)idx * 2 + 0];
    float ci = C_r[(size_t)idx * 2 + 1];
    gXr[idx] = tf32r(cr * xr - ci * xi);
    gXi[idx] = tf32r(cr * xi + ci * xr);
}

// ------------------------- main -------------------------
extern __shared__ char dyn_smem[];

__global__ void __launch_bounds__(256, 2)
main_kernel(const float* __restrict__ angle, const float* __restrict__ w,
            float* __restrict__ out) {
    __shared__ float2 sred[KT_CTA];

    const uint32_t XST = smem_u32(dyn_smem);
    const int tid  = threadIdx.x;
    const int lane = tid & 31;
    const int warp = tid >> 5;
    const int kw   = warp & 3;        // k-subtile (16 rows)
    const int nw   = warp >> 2;       // a-half of the 32-chunk (16 cols)
    const int r    = lane >> 2;
    const int q    = lane & 3;
    const int kblk = blockIdx.x * KT_CTA;

    // ---- per-thread E2 rotation seeds (A operand lives in registers) ----
    const int k0g = kblk + kw * 16 + r;     // A row r
    const int k1g = k0g + 8;                // A row r+8
    const float t0 = angle[2 * k0g + 1];
    const float t1 = angle[2 * k1g + 1];
    float i0ar, i0ai, i0br, i0bi, i1ar, i1ai, i1br, i1bi;   // init states
    float st0r, st0i, st1r, st1i;                            // step exp(i*8t)
    sincosf(t0 * (float)(q - 128),     &i0ai, &i0ar);
    sincosf(t0 * (float)(q + 4 - 128), &i0bi, &i0br);
    sincosf(t1 * (float)(q - 128),     &i1ai, &i1ar);
    sincosf(t1 * (float)(q + 4 - 128), &i1bi, &i1br);
    sincosf(8.0f * t0, &st0i, &st0r);
    sincosf(8.0f * t1, &st1i, &st1r);

    // ---- per-thread E1 constants (epilogue) ----
    const float s0 = angle[2 * k0g];
    const float s1 = angle[2 * k1g];
    float sttr[2], stti[2], advr[2], advi[2], facr[2][4], faci[2][4];
    {
        const float ss[2] = {s0, s1};
#pragma unroll
        for (int m = 0; m < 2; ++m) {
            sincosf(-128.0f * ss[m], &stti[m], &sttr[m]);
            sincosf(32.0f * ss[m], &advi[m], &advr[m]);
            const int co0 = nw * 16 + 2 * q;
#pragma unroll
            for (int idx = 0; idx < 4; ++idx) {
                int co = co0 + (idx >> 1) * 8 + (idx & 1);
                sincosf(ss[m] * (float)co, &faci[m][idx], &facr[m][idx]);
            }
        }
    }
    const float wk0 = w[k0g & (NVEC - 1)];
    const float wk1 = w[k1g & (NVEC - 1)];

    // ---- stage loader: st -> (c = st>>5, ach = (st>>2)&7, qtr = st&3) ----
    const int lcol  = tid >> 3;         // 0..31 a-col
    const int lpart = tid & 7;          // 8-float segment in b
    auto issue_load = [&](int st) {
        uint32_t dst = XST + (uint32_t)(st & 3) * XBUF
                     + (uint32_t)(lcol * COLSTR + lpart * 8) * 4;
        size_t src = ((size_t)(((st >> 5) << 8) + (((st >> 2) & 7) << 5) + lcol) << 8)
                   + ((st & 3) << 6) + lpart * 8;
        const float* pr = gXr + src;
        const float* pi = gXi + src;
        cp16(dst,              pr);
        cp16(dst + 16,         pr + 4);
        cp16(dst + PLANE,      pi);
        cp16(dst + PLANE + 16, pi + 4);
        CP_COMMIT();
    };

    // rotation states + accumulators
    float e0ar, e0ai, e0br, e0bi, e1ar, e1ai, e1br, e1bi;
    float acc[2][4][4];
    float y0r = 0.f, y0i = 0.f, y1r = 0.f, y1i = 0.f;
    float str_[2] = {sttr[0], sttr[1]}, sti_[2] = {stti[0], stti[1]};

    issue_load(0); issue_load(1); issue_load(2);

#pragma unroll 1
    for (int st = 0; st < NSTAGE; ++st) {
        CP_WAIT(2);            // stage st resident
        __syncthreads();       // everyone done with buf (st+3)&3's old data
        if (st + 3 < NSTAGE) issue_load(st + 3); else CP_COMMIT();

        if ((st & 3) == 0) {   // new a-chunk: reset E2 states + accumulators
            e0ar = i0ar; e0ai = i0ai; e0br = i0br; e0bi = i0bi;
            e1ar = i1ar; e1ai = i1ai; e1br = i1br; e1bi = i1bi;
#pragma unroll
            for (int nt = 0; nt < 2; ++nt)
#pragma unroll
                for (int p = 0; p < 4; ++p)
#pragma unroll
                    for (int e = 0; e < 4; ++e) acc[nt][p][e] = 0.f;
        }

        const uint32_t xb = XST + (uint32_t)(st & 3) * XBUF;
        uint32_t bA0 = xb + (uint32_t)((nw * 16 + r) * COLSTR + q) * 4;
        uint32_t bA1 = bA0 + 8 * COLSTR * 4;

#pragma unroll 4
        for (int bs = 0; bs < 8; ++bs) {
            uint32_t Ar[4], Ai[4];
            Ar[0] = tf32u(e0ar); Ai[0] = tf32u(e0ai);
            Ar[1] = tf32u(e1ar); Ai[1] = tf32u(e1ai);
            Ar[2] = tf32u(e0br); Ai[2] = tf32u(e0bi);
            Ar[3] = tf32u(e1br); Ai[3] = tf32u(e1bi);

            uint32_t b0r = lds1(bA0),         b0r4 = lds1(bA0 + 16);
            uint32_t b0i = lds1(bA0 + PLANE), b0i4 = lds1(bA0 + PLANE + 16);
            uint32_t b1r = lds1(bA1),         b1r4 = lds1(bA1 + 16);
            uint32_t b1i = lds1(bA1 + PLANE), b1i4 = lds1(bA1 + PLANE + 16);

            mma8(acc[0][0], Ar, b0r, b0r4);
            mma8(acc[0][1], Ar, b0i, b0i4);
            mma8(acc[0][2], Ai, b0r, b0r4);
            mma8(acc[0][3], Ai, b0i, b0i4);
            mma8(acc[1][0], Ar, b1r, b1r4);
            mma8(acc[1][1], Ar, b1i, b1i4);
            mma8(acc[1][2], Ai, b1r, b1r4);
            mma8(acc[1][3], Ai, b1i, b1i4);

            // rotate E2 states by exp(i*8t)
            float nr;
            nr = e0ar * st0r - e0ai * st0i; e0ai = fmaf(e0ar, st0i, e0ai * st0r); e0ar = nr;
            nr = e0br * st0r - e0bi * st0i; e0bi = fmaf(e0br, st0i, e0bi * st0r); e0br = nr;
            nr = e1ar * st1r - e1ai * st1i; e1ai = fmaf(e1ar, st1i, e1ai * st1r); e1ar = nr;
            nr = e1br * st1r - e1bi * st1i; e1bi = fmaf(e1br, st1i, e1bi * st1r); e1br = nr;

            bA0 += 32; bA1 += 32;
        }

        if ((st & 3) == 3) {
            // ---- epilogue: y += e1 * T for this 32-a chunk ----
#pragma unroll
            for (int nt = 0; nt < 2; ++nt)
#pragma unroll
                for (int m = 0; m < 2; ++m)
#pragma unroll
                    for (int j = 0; j < 2; ++j) {
                        int e = m * 2 + j;
                        float Tr = acc[nt][0][e] - acc[nt][3][e];
                        float Ti = acc[nt][1][e] + acc[nt][2][e];
                        int idx = nt * 2 + j;
                        float er = str_[m] * facr[m][idx] - sti_[m] * faci[m][idx];
                        float ei = str_[m] * faci[m][idx] + sti_[m] * facr[m][idx];
                        if (m == 0) {
                            y0r = fmaf(er, Tr, y0r); y0r = fmaf(-ei, Ti, y0r);
                            y0i = fmaf(er, Ti, y0i); y0i = fmaf(ei, Tr, y0i);
                        } else {
                            y1r = fmaf(er, Tr, y1r); y1r = fmaf(-ei, Ti, y1r);
                            y1i = fmaf(er, Ti, y1i); y1i = fmaf(ei, Tr, y1i);
                        }
                    }
#pragma unroll
            for (int m = 0; m < 2; ++m) {
                float nr = str_[m] * advr[m] - sti_[m] * advi[m];
                sti_[m] = fmaf(str_[m], advi[m], sti_[m] * advr[m]);
                str_[m] = nr;
            }

            if ((st & 31) == 31) {
                // ---- coil done: reduce over q lanes + nw warps, store ----
                int c = st >> 5;
                y0r += __shfl_xor_sync(0xffffffff, y0r, 1);
                y0r += __shfl_xor_sync(0xffffffff, y0r, 2);
                y0i += __shfl_xor_sync(0xffffffff, y0i, 1);
                y0i += __shfl_xor_sync(0xffffffff, y0i, 2);
                y1r += __shfl_xor_sync(0xffffffff, y1r, 1);
                y1r += __shfl_xor_sync(0xffffffff, y1r, 2);
                y1i += __shfl_xor_sync(0xffffffff, y1i, 1);
                y1i += __shfl_xor_sync(0xffffffff, y1i, 2);

                if (nw == 1 && q == 0) {
                    sred[kw * 16 + r]     = make_float2(y0r, y0i);
                    sred[kw * 16 + 8 + r] = make_float2(y1r, y1i);
                }
                __syncthreads();
                if (nw == 0 && q == 0) {
                    float2 p0 = sred[kw * 16 + r];
                    float2 p1 = sred[kw * 16 + 8 + r];
                    size_t o0 = ((size_t)c * KTOT + k0g) * 2;
                    size_t o1 = ((size_t)c * KTOT + k1g) * 2;
                    out[o0 + 0] = (y0r + p0.x) * wk0;
                    out[o0 + 1] = (y0i + p0.y) * wk0;
                    out[o1 + 0] = (y1r + p1.x) * wk1;
                    out[o1 + 1] = (y1i + p1.y) * wk1;
                }
                y0r = y0i = y1r = y1i = 0.f;
#pragma unroll
                for (int m = 0; m < 2; ++m) { str_[m] = sttr[m]; sti_[m] = stti[m]; }
            }
        }
    }
}

// ------------------------- launch -------------------------
extern "C" void kernel_launch(void* const* d_in, const int* in_sizes, int n_in,
                              void* d_out, int out_size) {
    const float* input_r = (const float*)d_in[0];
    const float* C_r     = (const float*)d_in[1];
    const float* w       = (const float*)d_in[2];
    const float* angle   = (const float*)d_in[3];
    float* out = (float*)d_out;

    prep_X<<<(NCOIL * NN * NN + 255) / 256, 256>>>(input_r, C_r);

    cudaFuncSetAttribute(main_kernel,
                         cudaFuncAttributeMaxDynamicSharedMemorySize, SMEM_BYTES);
    main_kernel<<<NCTA, 256, SMEM_BYTES>>>(angle, w, out);
}

// round 5
// speedup vs baseline: 10.0061x; 1.3889x over previous
#include <cuda_runtime.h>
#include <cstdint>
#include <math.h>

#define NN     256
#define NCOIL  8
#define KTOT   17408
#define NVEC   512
#define KT_CTA 64
#define NCTA   (KTOT / KT_CTA)     // 272

// smem layout (bytes): per coil: region A (32 a-cols x 320B) + region B (32 x 160B)
#define SA     320                 // 80 words/col: 16 pairs x [xr0,xr1,-xi0,-xi1] + pad
#define SB     160                 // 40 words/col: 16 pairs x [xi0,xi1] + pad
#define ASZ    (32 * SA)           // 10240
#define BSZ    (32 * SB)           // 5120
#define COILB  (ASZ + BSZ)         // 15360
#define STAGEB (2 * COILB)         // 30720 (2 coils)
#define NBUF   3
#define SMEM_BYTES (NBUF * STAGEB) // 92160
#define NSTAGE 256                 // 4 coil-pairs x 8 ach x 8 bq
#define SLAB   3072                // floats per (coil, ach, bq) slab = 32*96

// Global scratch: packed Xc, layout [c][ach][bq][a-local(32)][96 floats]
//   words 0..63:  pairs p=bs*4+q: [Xr(b0), Xr(b1), -Xi(b0), -Xi(b1)]  (b1=b0+4)
//   words 64..95: pairs:          [Xi(b0), Xi(b1)]
__device__ float gX[(size_t)NCOIL * 64 * SLAB];

// ------------------------- helpers -------------------------
__device__ __forceinline__ uint32_t smem_u32(const void* p) {
    uint32_t a;
    asm("{ .reg .u64 t; cvta.to.shared.u64 t, %1; cvt.u32.u64 %0, t; }"
        : "=r"(a) : "l"(p));
    return a;
}
__device__ __forceinline__ float tf32r(float x) {
    uint32_t u;
    asm("cvt.rna.tf32.f32 %0, %1;" : "=r"(u) : "f"(x));
    return __uint_as_float(u);
}
__device__ __forceinline__ void cp16(uint32_t dst, const float* src) {
    asm volatile("cp.async.cg.shared.global [%0], [%1], 16;"
                 :: "r"(dst), "l"(src) : "memory");
}
#define CP_COMMIT() asm volatile("cp.async.commit_group;" ::: "memory")
#define CP_WAIT(n)  asm volatile("cp.async.wait_group %0;" :: "n"(n) : "memory")

__device__ __forceinline__ void lds128(uint32_t& a, uint32_t& b, uint32_t& c,
                                       uint32_t& d, uint32_t addr) {
    asm("ld.shared.v4.b32 {%0,%1,%2,%3}, [%4];"
        : "=r"(a), "=r"(b), "=r"(c), "=r"(d) : "r"(addr));
}
__device__ __forceinline__ void lds64(uint32_t& a, uint32_t& b, uint32_t addr) {
    asm("ld.shared.v2.b32 {%0,%1}, [%2];" : "=r"(a), "=r"(b) : "r"(addr));
}
__device__ __forceinline__ void mma8(float* d, const uint32_t* A,
                                     uint32_t b0, uint32_t b1) {
    asm volatile(
        "mma.sync.aligned.m16n8k8.row.col.f32.tf32.tf32.f32 "
        "{%0,%1,%2,%3}, {%4,%5,%6,%7}, {%8,%9}, {%0,%1,%2,%3};"
        : "+f"(d[0]), "+f"(d[1]), "+f"(d[2]), "+f"(d[3])
        : "r"(A[0]), "r"(A[1]), "r"(A[2]), "r"(A[3]), "r"(b0), "r"(b1));
}

// ------------------------- prep -------------------------
__global__ void prep_X(const float* __restrict__ input_r,
                       const float* __restrict__ C_r) {
    int idx = blockIdx.x * blockDim.x + threadIdx.x;   // (c*256+a)*256 + b
    if (idx >= NCOIL * NN * NN) return;
    int c = idx >> 16;
    int a = (idx >> 8) & 255;
    int b = idx & 255;
    float xr = input_r[(a * NN + b) * 2 + 0];
    float xi = input_r[(a * NN + b) * 2 + 1];
    float cr = C_r[(size_t)idx * 2 + 0];
    float ci = C_r[(size_t)idx * 2 + 1];
    float Xr = tf32r(cr * xr - ci * xi);
    float Xi = tf32r(cr * xi + ci * xr);
    int bq = b >> 5, bs = (b >> 3) & 3, q = b & 3, e = (b >> 2) & 1;
    int p = bs * 4 + q;
    size_t base = ((((size_t)c * 8 + (a >> 5)) * 8 + bq) * 32 + (a & 31)) * 96;
    gX[base + p * 4 + e]     = Xr;
    gX[base + p * 4 + 2 + e] = -Xi;
    gX[base + 64 + p * 2 + e] = Xi;
}

// ------------------------- main -------------------------
extern __shared__ char dyn_smem[];

__global__ void __launch_bounds__(256, 2)
main_kernel(const float* __restrict__ angle, const float* __restrict__ w,
            float* __restrict__ out) {
    __shared__ float2 sred[2][KT_CTA];

    const uint32_t XST = smem_u32(dyn_smem);
    const int tid  = threadIdx.x;
    const int lane = tid & 31;
    const int warp = tid >> 5;
    const int kw   = warp & 3;
    const int nw   = warp >> 2;
    const int r    = lane >> 2;
    const int q    = lane & 3;
    const int kblk = blockIdx.x * KT_CTA;

    const int k0g = kblk + kw * 16 + r;
    const int k1g = k0g + 8;
    const float t0 = angle[2 * k0g + 1];
    const float t1 = angle[2 * k1g + 1];

    // E2 seeds (scaled to center HW tf32 truncation) + per-8b rotation steps
    const float SC = 1.00024414f;
    float i0ar, i0ai, i0br, i0bi, i1ar, i1ai, i1br, i1bi;
    {
        float s_, c_;
        sincosf(t0 * (float)(q - 128), &s_, &c_); i0ar = c_ * SC; i0ai = s_ * SC;
        sincosf(t0 * (float)(q - 124), &s_, &c_); i0br = c_ * SC; i0bi = s_ * SC;
        sincosf(t1 * (float)(q - 128), &s_, &c_); i1ar = c_ * SC; i1ai = s_ * SC;
        sincosf(t1 * (float)(q - 124), &s_, &c_); i1br = c_ * SC; i1bi = s_ * SC;
    }
    float st0r, st0i, st1r, st1i;
    sincosf(8.0f * t0, &st0i, &st0r);
    sincosf(8.0f * t1, &st1i, &st1r);

    // E1 epilogue constants
    const float s0 = angle[2 * k0g];
    const float s1 = angle[2 * k1g];
    float sttr[2], stti[2], advr[2], advi[2], facr[2][4], faci[2][4];
    {
        const float ss[2] = {s0, s1};
#pragma unroll
        for (int m = 0; m < 2; ++m) {
            sincosf(-128.0f * ss[m], &stti[m], &sttr[m]);
            sincosf(32.0f * ss[m], &advi[m], &advr[m]);
            const int co0 = nw * 16 + 2 * q;
#pragma unroll
            for (int idx = 0; idx < 4; ++idx) {
                int co = co0 + (idx >> 1) * 8 + (idx & 1);
                sincosf(ss[m] * (float)co, &faci[m][idx], &facr[m][idx]);
            }
        }
    }
    const float wk0 = w[k0g & (NVEC - 1)];
    const float wk1 = w[k1g & (NVEC - 1)];

    // loader precompute: 1536 16B-chunks/stage, 6 per thread
    uint32_t dstoff[6];
    int srcoff[6];
#pragma unroll
    for (int j = 0; j < 6; ++j) {
        int ch  = tid + j * 256;
        int ci  = (ch >= 768) ? 1 : 0;
        int loc = ch - ci * 768;
        int al  = loc / 24;
        int kk  = loc - al * 24;
        srcoff[j] = ci * (64 * SLAB) + loc * 4;
        dstoff[j] = (uint32_t)(ci * COILB +
                    (kk < 16 ? al * SA + kk * 16 : ASZ + al * SB + (kk - 16) * 16));
    }
    auto issue_load = [&](int st, int buf) {
        int cp_ = st >> 6, ach = (st >> 3) & 7, bq = st & 7;
        const float* src = gX + (size_t)(((cp_ * 16 + ach) * 8 + bq)) * SLAB;
        uint32_t dst = XST + (uint32_t)buf * STAGEB;
#pragma unroll
        for (int j = 0; j < 6; ++j) cp16(dst + dstoff[j], src + srcoff[j]);
        CP_COMMIT();
    };

    float yr[2][2] = {}, yi[2][2] = {};
    float runr[2] = {sttr[0], sttr[1]}, runi[2] = {stti[0], stti[1]};

    issue_load(0, 0);
    issue_load(1, 1);
    int st = 0, buf = 0;

#pragma unroll 1
    for (int cp = 0; cp < 4; ++cp) {
#pragma unroll 1
        for (int ach = 0; ach < 8; ++ach) {
            float e0ar = i0ar, e0ai = i0ai, e0br = i0br, e0bi = i0bi;
            float e1ar = i1ar, e1ai = i1ai, e1br = i1br, e1bi = i1bi;
            float accR[2][2][4] = {}, accI[2][2][4] = {};

#pragma unroll 1
            for (int bq = 0; bq < 8; ++bq) {
                CP_WAIT(1);
                __syncthreads();
                {
                    int nb = buf + 2; if (nb >= 3) nb -= 3;
                    if (st + 2 < NSTAGE) issue_load(st + 2, nb);
                    else                 CP_COMMIT();
                }
                const uint32_t aA = XST + (uint32_t)buf * STAGEB
                                  + (uint32_t)(nw * 16 + r) * SA + q * 16;
                const uint32_t aB = XST + (uint32_t)buf * STAGEB + ASZ
                                  + (uint32_t)(nw * 16 + r) * SB + q * 8;
#pragma unroll
                for (int bs = 0; bs < 4; ++bs) {
                    uint32_t Ar[4], Ai[4];
                    Ar[0] = __float_as_uint(e0ar); Ar[1] = __float_as_uint(e1ar);
                    Ar[2] = __float_as_uint(e0br); Ar[3] = __float_as_uint(e1br);
                    Ai[0] = __float_as_uint(e0ai); Ai[1] = __float_as_uint(e1ai);
                    Ai[2] = __float_as_uint(e0bi); Ai[3] = __float_as_uint(e1bi);
#pragma unroll
                    for (int ci = 0; ci < 2; ++ci)
#pragma unroll
                        for (int nt = 0; nt < 2; ++nt) {
                            uint32_t xr0, xr1, mi0, mi1, xi0, xi1;
                            lds128(xr0, xr1, mi0, mi1,
                                   aA + ci * COILB + nt * (8 * SA) + bs * 64);
                            lds64(xi0, xi1,
                                  aB + ci * COILB + nt * (8 * SB) + bs * 32);
                            mma8(accR[ci][nt], Ar, xr0, xr1);
                            mma8(accI[ci][nt], Ar, xi0, xi1);
                            mma8(accR[ci][nt], Ai, mi0, mi1);
                            mma8(accI[ci][nt], Ai, xr0, xr1);
                        }
                    float nr;
                    nr = e0ar * st0r - e0ai * st0i; e0ai = fmaf(e0ar, st0i, e0ai * st0r); e0ar = nr;
                    nr = e0br * st0r - e0bi * st0i; e0bi = fmaf(e0br, st0i, e0bi * st0r); e0br = nr;
                    nr = e1ar * st1r - e1ai * st1i; e1ai = fmaf(e1ar, st1i, e1ai * st1r); e1ar = nr;
                    nr = e1br * st1r - e1bi * st1i; e1bi = fmaf(e1br, st1i, e1bi * st1r); e1br = nr;
                }
                ++st; ++buf; if (buf == 3) buf = 0;
            }

            // epilogue: y += e1 * T for this 32-a chunk (both coils share e1)
#pragma unroll
            for (int nt = 0; nt < 2; ++nt)
#pragma unroll
                for (int m = 0; m < 2; ++m)
#pragma unroll
                    for (int j = 0; j < 2; ++j) {
                        int e = m * 2 + j, idx = nt * 2 + j;
                        float er = runr[m] * facr[m][idx] - runi[m] * faci[m][idx];
                        float ei = runr[m] * faci[m][idx] + runi[m] * facr[m][idx];
#pragma unroll
                        for (int ci = 0; ci < 2; ++ci) {
                            float Tr = accR[ci][nt][e], Ti = accI[ci][nt][e];
                            yr[ci][m] = fmaf(er, Tr, yr[ci][m]);
                            yr[ci][m] = fmaf(-ei, Ti, yr[ci][m]);
                            yi[ci][m] = fmaf(er, Ti, yi[ci][m]);
                            yi[ci][m] = fmaf(ei, Tr, yi[ci][m]);
                        }
                    }
#pragma unroll
            for (int m = 0; m < 2; ++m) {
                float nr = runr[m] * advr[m] - runi[m] * advi[m];
                runi[m] = fmaf(runr[m], advi[m], runi[m] * advr[m]);
                runr[m] = nr;
            }
        }

        // ---- writeout coil pair cp ----
#pragma unroll
        for (int ci = 0; ci < 2; ++ci)
#pragma unroll
            for (int m = 0; m < 2; ++m) {
                yr[ci][m] += __shfl_xor_sync(0xffffffffu, yr[ci][m], 1);
                yr[ci][m] += __shfl_xor_sync(0xffffffffu, yr[ci][m], 2);
                yi[ci][m] += __shfl_xor_sync(0xffffffffu, yi[ci][m], 1);
                yi[ci][m] += __shfl_xor_sync(0xffffffffu, yi[ci][m], 2);
            }
        if (nw == 1 && q == 0) {
            sred[0][kw * 16 + r]     = make_float2(yr[0][0], yi[0][0]);
            sred[0][kw * 16 + 8 + r] = make_float2(yr[0][1], yi[0][1]);
            sred[1][kw * 16 + r]     = make_float2(yr[1][0], yi[1][0]);
            sred[1][kw * 16 + 8 + r] = make_float2(yr[1][1], yi[1][1]);
        }
        __syncthreads();
        if (nw == 0 && q == 0) {
            int c0 = cp * 2;
#pragma unroll
            for (int ci = 0; ci < 2; ++ci) {
                float2 p0 = sred[ci][kw * 16 + r];
                float2 p1 = sred[ci][kw * 16 + 8 + r];
                size_t o0 = ((size_t)(c0 + ci) * KTOT + k0g) * 2;
                size_t o1 = ((size_t)(c0 + ci) * KTOT + k1g) * 2;
                out[o0 + 0] = (yr[ci][0] + p0.x) * wk0;
                out[o0 + 1] = (yi[ci][0] + p0.y) * wk0;
                out[o1 + 0] = (yr[ci][1] + p1.x) * wk1;
                out[o1 + 1] = (yi[ci][1] + p1.y) * wk1;
            }
        }
#pragma unroll
        for (int ci = 0; ci < 2; ++ci)
#pragma unroll
            for (int m = 0; m < 2; ++m) { yr[ci][m] = 0.f; yi[ci][m] = 0.f; }
#pragma unroll
        for (int m = 0; m < 2; ++m) { runr[m] = sttr[m]; runi[m] = stti[m]; }
    }
}

// ------------------------- launch -------------------------
extern "C" void kernel_launch(void* const* d_in, const int* in_sizes, int n_in,
                              void* d_out, int out_size) {
    const float* input_r = (const float*)d_in[0];
    const float* C_r     = (const float*)d_in[1];
    const float* w       = (const float*)d_in[2];
    const float* angle   = (const float*)d_in[3];
    float* out = (float*)d_out;

    prep_X<<<(NCOIL * NN * NN + 255) / 256, 256>>>(input_r, C_r);

    cudaFuncSetAttribute(main_kernel,
                         cudaFuncAttributeMaxDynamicSharedMemorySize, SMEM_BYTES);
    main_kernel<<<NCTA, 256, SMEM_BYTES>>>(angle, w, out);
}

// round 6
// speedup vs baseline: 11.0713x; 1.1065x over previous
#include <cuda_runtime.h>
#include <cstdint>
#include <math.h>

#define NN     256
#define NCOIL  8
#define KTOT   17408
#define NVEC   512
#define KT_CTA 64
#define NCTA   (KTOT / KT_CTA)     // 272

// smem per coil: region A (32 cols x 320B: [xr0,xr1,xi0,xi1] pairs) +
//                region B (32 cols x 160B: [xs0,xs1] pairs)
#define SA     320
#define SB     160
#define ASZ    (32 * SA)           // 10240
#define BSZ    (32 * SB)           // 5120
#define COILB  (ASZ + BSZ)         // 15360
#define STAGEB (2 * COILB)         // 30720 (2 coils)
#define NBUF   3
#define SMEM_BYTES (NBUF * STAGEB) // 92160
#define NSTAGE 256                 // 4 coil-pairs x 8 ach x 8 bq
#define SLAB   3072                // floats per (coil, ach, bq) slab = 32*96

// packed Xc: [c][ach][bq][a-local(32)][96 words]
//   words 0..63:  pairs p: [Xr(b0), Xr(b1), Xi(b0), Xi(b1)]   (b1=b0+4)
//   words 64..95: pairs p: [Xs(b0), Xs(b1)]   Xs = tf32(Xr+Xi)
__device__ float gX[(size_t)NCOIL * 64 * SLAB];

// ------------------------- helpers -------------------------
__device__ __forceinline__ uint32_t smem_u32(const void* p) {
    uint32_t a;
    asm("{ .reg .u64 t; cvta.to.shared.u64 t, %1; cvt.u32.u64 %0, t; }"
        : "=r"(a) : "l"(p));
    return a;
}
__device__ __forceinline__ float tf32r(float x) {
    uint32_t u;
    asm("cvt.rna.tf32.f32 %0, %1;" : "=r"(u) : "f"(x));
    return __uint_as_float(u);
}
__device__ __forceinline__ void cp16(uint32_t dst, const float* src) {
    asm volatile("cp.async.cg.shared.global [%0], [%1], 16;"
                 :: "r"(dst), "l"(src) : "memory");
}
#define CP_COMMIT() asm volatile("cp.async.commit_group;" ::: "memory")
#define CP_WAIT(n)  asm volatile("cp.async.wait_group %0;" :: "n"(n) : "memory")

__device__ __forceinline__ void lds128(uint32_t& a, uint32_t& b, uint32_t& c,
                                       uint32_t& d, uint32_t addr) {
    asm("ld.shared.v4.b32 {%0,%1,%2,%3}, [%4];"
        : "=r"(a), "=r"(b), "=r"(c), "=r"(d) : "r"(addr));
}
__device__ __forceinline__ void lds64(uint32_t& a, uint32_t& b, uint32_t addr) {
    asm("ld.shared.v2.b32 {%0,%1}, [%2];" : "=r"(a), "=r"(b) : "r"(addr));
}
__device__ __forceinline__ void mma8(float* d, const uint32_t* A,
                                     uint32_t b0, uint32_t b1) {
    asm volatile(
        "mma.sync.aligned.m16n8k8.row.col.f32.tf32.tf32.f32 "
        "{%0,%1,%2,%3}, {%4,%5,%6,%7}, {%8,%9}, {%0,%1,%2,%3};"
        : "+f"(d[0]), "+f"(d[1]), "+f"(d[2]), "+f"(d[3])
        : "r"(A[0]), "r"(A[1]), "r"(A[2]), "r"(A[3]), "r"(b0), "r"(b1));
}

// ------------------------- prep -------------------------
__global__ void prep_X(const float* __restrict__ input_r,
                       const float* __restrict__ C_r) {
    int idx = blockIdx.x * blockDim.x + threadIdx.x;   // (c*256+a)*256 + b
    if (idx >= NCOIL * NN * NN) return;
    int c = idx >> 16;
    int a = (idx >> 8) & 255;
    int b = idx & 255;
    float xr = input_r[(a * NN + b) * 2 + 0];
    float xi = input_r[(a * NN + b) * 2 + 1];
    float cr = C_r[(size_t)idx * 2 + 0];
    float ci = C_r[(size_t)idx * 2 + 1];
    float Xr = tf32r(cr * xr - ci * xi);
    float Xi = tf32r(cr * xi + ci * xr);
    float Xs = tf32r(Xr + Xi);
    int bq = b >> 5, bs = (b >> 3) & 3, q = b & 3, e = (b >> 2) & 1;
    int p = bs * 4 + q;
    size_t base = ((((size_t)c * 8 + (a >> 5)) * 8 + bq) * 32 + (a & 31)) * 96;
    gX[base + p * 4 + e]      = Xr;
    gX[base + p * 4 + 2 + e]  = Xi;
    gX[base + 64 + p * 2 + e] = Xs;
}

// ------------------------- main -------------------------
extern __shared__ char dyn_smem[];

__global__ void __launch_bounds__(256, 2)
main_kernel(const float* __restrict__ angle, const float* __restrict__ w,
            float* __restrict__ out) {
    __shared__ float2 sred[2][KT_CTA];

    const uint32_t XST = smem_u32(dyn_smem);
    const int tid  = threadIdx.x;
    const int lane = tid & 31;
    const int warp = tid >> 5;
    const int kw   = warp & 3;
    const int nw   = warp >> 2;
    const int r    = lane >> 2;
    const int q    = lane & 3;
    const int kblk = blockIdx.x * KT_CTA;

    const int k0g = kblk + kw * 16 + r;
    const int k1g = k0g + 8;
    const float t0 = angle[2 * k0g + 1];
    const float t1 = angle[2 * k1g + 1];

    // E2 seeds (scaled to center HW tf32 truncation) + per-8b rotation steps
    const float SC = 1.00024414f;
    float i0ar, i0ai, i0br, i0bi, i1ar, i1ai, i1br, i1bi;
    {
        float s_, c_;
        sincosf(t0 * (float)(q - 128), &s_, &c_); i0ar = c_ * SC; i0ai = s_ * SC;
        sincosf(t0 * (float)(q - 124), &s_, &c_); i0br = c_ * SC; i0bi = s_ * SC;
        sincosf(t1 * (float)(q - 128), &s_, &c_); i1ar = c_ * SC; i1ai = s_ * SC;
        sincosf(t1 * (float)(q - 124), &s_, &c_); i1br = c_ * SC; i1bi = s_ * SC;
    }
    float st0r, st0i, st1r, st1i;
    sincosf(8.0f * t0, &st0i, &st0r);
    sincosf(8.0f * t1, &st1i, &st1r);

    // E1 epilogue constants (compact set: 12 regs)
    const float s0 = angle[2 * k0g];
    const float s1 = angle[2 * k1g];
    float sttr[2], stti[2], advr[2], advi[2];
    float fc0r[2], fc0i[2], f1r[2], f1i[2], f8r[2], f8i[2];
    {
        const float ss[2] = {s0, s1};
        const int co0 = nw * 16 + 2 * q;
#pragma unroll
        for (int m = 0; m < 2; ++m) {
            sincosf(-128.0f * ss[m], &stti[m], &sttr[m]);
            sincosf(32.0f * ss[m], &advi[m], &advr[m]);
            sincosf(ss[m] * (float)co0, &fc0i[m], &fc0r[m]);
            sincosf(ss[m], &f1i[m], &f1r[m]);
            sincosf(8.0f * ss[m], &f8i[m], &f8r[m]);
        }
    }
    const float wk0 = w[k0g & (NVEC - 1)];
    const float wk1 = w[k1g & (NVEC - 1)];

    // loader: 1536 16B-chunks/stage, 6 per thread; offsets recomputed per call
    auto issue_load = [&](int st, int buf) {
        int cp_ = st >> 6, ach = (st >> 3) & 7, bq = st & 7;
        const float* src = gX + (size_t)((cp_ * 16 + ach) * 8 + bq) * SLAB;
        uint32_t dst = XST + (uint32_t)buf * STAGEB;
#pragma unroll
        for (int j = 0; j < 6; ++j) {
            int ch  = tid + j * 256;
            int ci  = (ch >= 768) ? 1 : 0;
            int loc = ch - ci * 768;
            int al  = loc / 24;
            int kk  = loc - al * 24;
            uint32_t doff = (uint32_t)(ci * COILB +
                (kk < 16 ? al * SA + kk * 16 : ASZ + al * SB + (kk - 16) * 16));
            cp16(dst + doff, src + ci * (64 * SLAB) + loc * 4);
        }
        CP_COMMIT();
    };

    float yr[2][2] = {}, yi[2][2] = {};
    float runr[2] = {sttr[0], sttr[1]}, runi[2] = {stti[0], stti[1]};

    issue_load(0, 0);
    issue_load(1, 1);
    int st = 0, buf = 0;

#pragma unroll 1
    for (int cp = 0; cp < 4; ++cp) {
#pragma unroll 1
        for (int ach = 0; ach < 8; ++ach) {
            float e0ar = i0ar, e0ai = i0ai, e0br = i0br, e0bi = i0bi;
            float e1ar = i1ar, e1ai = i1ai, e1br = i1br, e1bi = i1bi;
            float P1[2][2][4] = {}, P2[2][2][4] = {}, P3[2][2][4] = {};

#pragma unroll 1
            for (int bq = 0; bq < 8; ++bq) {
                CP_WAIT(1);
                __syncthreads();
                {
                    int nb = buf + 2; if (nb >= 3) nb -= 3;
                    if (st + 2 < NSTAGE) issue_load(st + 2, nb);
                    else                 CP_COMMIT();
                }
                const uint32_t aA = XST + (uint32_t)buf * STAGEB
                                  + (uint32_t)(nw * 16 + r) * SA + q * 16;
                const uint32_t aB = XST + (uint32_t)buf * STAGEB + ASZ
                                  + (uint32_t)(nw * 16 + r) * SB + q * 8;
#pragma unroll
                for (int bs = 0; bs < 4; ++bs) {
                    uint32_t Ar[4], Ai[4], As[4];
                    Ar[0] = __float_as_uint(e0ar); Ar[1] = __float_as_uint(e1ar);
                    Ar[2] = __float_as_uint(e0br); Ar[3] = __float_as_uint(e1br);
                    Ai[0] = __float_as_uint(e0ai); Ai[1] = __float_as_uint(e1ai);
                    Ai[2] = __float_as_uint(e0bi); Ai[3] = __float_as_uint(e1bi);
                    As[0] = __float_as_uint(e0ar + e0ai);
                    As[1] = __float_as_uint(e1ar + e1ai);
                    As[2] = __float_as_uint(e0br + e0bi);
                    As[3] = __float_as_uint(e1br + e1bi);
#pragma unroll
                    for (int ci = 0; ci < 2; ++ci)
#pragma unroll
                        for (int nt = 0; nt < 2; ++nt) {
                            uint32_t xr0, xr1, xi0, xi1, xs0, xs1;
                            lds128(xr0, xr1, xi0, xi1,
                                   aA + ci * COILB + nt * (8 * SA) + bs * 64);
                            lds64(xs0, xs1,
                                  aB + ci * COILB + nt * (8 * SB) + bs * 32);
                            mma8(P1[ci][nt], Ar, xr0, xr1);
                            mma8(P2[ci][nt], Ai, xi0, xi1);
                            mma8(P3[ci][nt], As, xs0, xs1);
                        }
                    float nr;
                    nr = e0ar * st0r - e0ai * st0i; e0ai = fmaf(e0ar, st0i, e0ai * st0r); e0ar = nr;
                    nr = e0br * st0r - e0bi * st0i; e0bi = fmaf(e0br, st0i, e0bi * st0r); e0br = nr;
                    nr = e1ar * st1r - e1ai * st1i; e1ai = fmaf(e1ar, st1i, e1ai * st1r); e1ar = nr;
                    nr = e1br * st1r - e1bi * st1i; e1bi = fmaf(e1br, st1i, e1bi * st1r); e1br = nr;
                }
                ++st; ++buf; if (buf == 3) buf = 0;
            }

            // ---- epilogue: y += e1 * T, T from 3M combine ----
#pragma unroll
            for (int m = 0; m < 2; ++m) {
                // base factor: run * exp(i s co0)
                float b0r = runr[m] * fc0r[m] - runi[m] * fc0i[m];
                float b0i = runr[m] * fc0i[m] + runi[m] * fc0r[m];
#pragma unroll
                for (int nt = 0; nt < 2; ++nt) {
                    float cr_ = b0r, ci_ = b0i;
                    if (nt == 1) {
                        cr_ = b0r * f8r[m] - b0i * f8i[m];
                        ci_ = b0r * f8i[m] + b0i * f8r[m];
                    }
#pragma unroll
                    for (int j = 0; j < 2; ++j) {
                        float er = cr_, ei = ci_;
                        if (j == 1) {
                            er = cr_ * f1r[m] - ci_ * f1i[m];
                            ei = cr_ * f1i[m] + ci_ * f1r[m];
                        }
                        int e = m * 2 + j;
#pragma unroll
                        for (int ci2 = 0; ci2 < 2; ++ci2) {
                            float p1 = P1[ci2][nt][e], p2 = P2[ci2][nt][e];
                            float Tr = p1 - p2;
                            float Ti = P3[ci2][nt][e] - p1 - p2;
                            yr[ci2][m] = fmaf(er, Tr, yr[ci2][m]);
                            yr[ci2][m] = fmaf(-ei, Ti, yr[ci2][m]);
                            yi[ci2][m] = fmaf(er, Ti, yi[ci2][m]);
                            yi[ci2][m] = fmaf(ei, Tr, yi[ci2][m]);
                        }
                    }
                }
            }
#pragma unroll
            for (int m = 0; m < 2; ++m) {
                float nr = runr[m] * advr[m] - runi[m] * advi[m];
                runi[m] = fmaf(runr[m], advi[m], runi[m] * advr[m]);
                runr[m] = nr;
            }
        }

        // ---- writeout coil pair cp ----
#pragma unroll
        for (int ci = 0; ci < 2; ++ci)
#pragma unroll
            for (int m = 0; m < 2; ++m) {
                yr[ci][m] += __shfl_xor_sync(0xffffffffu, yr[ci][m], 1);
                yr[ci][m] += __shfl_xor_sync(0xffffffffu, yr[ci][m], 2);
                yi[ci][m] += __shfl_xor_sync(0xffffffffu, yi[ci][m], 1);
                yi[ci][m] += __shfl_xor_sync(0xffffffffu, yi[ci][m], 2);
            }
        if (nw == 1 && q == 0) {
            sred[0][kw * 16 + r]     = make_float2(yr[0][0], yi[0][0]);
            sred[0][kw * 16 + 8 + r] = make_float2(yr[0][1], yi[0][1]);
            sred[1][kw * 16 + r]     = make_float2(yr[1][0], yi[1][0]);
            sred[1][kw * 16 + 8 + r] = make_float2(yr[1][1], yi[1][1]);
        }
        __syncthreads();
        if (nw == 0 && q == 0) {
            int c0 = cp * 2;
#pragma unroll
            for (int ci = 0; ci < 2; ++ci) {
                float2 p0 = sred[ci][kw * 16 + r];
                float2 p1 = sred[ci][kw * 16 + 8 + r];
                size_t o0 = ((size_t)(c0 + ci) * KTOT + k0g) * 2;
                size_t o1 = ((size_t)(c0 + ci) * KTOT + k1g) * 2;
                out[o0 + 0] = (yr[ci][0] + p0.x) * wk0;
                out[o0 + 1] = (yi[ci][0] + p0.y) * wk0;
                out[o1 + 0] = (yr[ci][1] + p1.x) * wk1;
                out[o1 + 1] = (yi[ci][1] + p1.y) * wk1;
            }
        }
#pragma unroll
        for (int ci = 0; ci < 2; ++ci)
#pragma unroll
            for (int m = 0; m < 2; ++m) { yr[ci][m] = 0.f; yi[ci][m] = 0.f; }
#pragma unroll
        for (int m = 0; m < 2; ++m) { runr[m] = sttr[m]; runi[m] = stti[m]; }
    }
}

// ------------------------- launch -------------------------
extern "C" void kernel_launch(void* const* d_in, const int* in_sizes, int n_in,
                              void* d_out, int out_size) {
    const float* input_r = (const float*)d_in[0];
    const float* C_r     = (const float*)d_in[1];
    const float* w       = (const float*)d_in[2];
    const float* angle   = (const float*)d_in[3];
    float* out = (float*)d_out;

    prep_X<<<(NCOIL * NN * NN + 255) / 256, 256>>>(input_r, C_r);

    cudaFuncSetAttribute(main_kernel,
                         cudaFuncAttributeMaxDynamicSharedMemorySize, SMEM_BYTES);
    main_kernel<<<NCTA, 256, SMEM_BYTES>>>(angle, w, out);
}